// round 15
// baseline (speedup 1.0000x reference)
#include <cuda_runtime.h>
#include <math.h>

typedef unsigned long long u64;

// ---------------- pretransposed tf32 weights (device scratch) ----------------
__device__ float g_WqT[16384];   // [c][j]  = tf32(Wq[j][c] * 1/sqrt(32))
__device__ float g_WkN[16384];   // [j][c]  = tf32(Wk[j][c])
__device__ float g_WvT[16384];   // [c][j]  = tf32(Wv[j][c])
__device__ float g_WoP[16384];   // [j][oc] = tf32(Wo[oc][(j&31)*4 + (j>>5)])
__device__ float g_Se1T[4096];   // [oc][i] = tf32(Wse1[i][oc])
__device__ float g_Se2T[4096];   // [i][oc] = tf32(Wse2[oc][i])
__device__ float g_bqs[128];     // bq * 1/sqrt(32)  (fp32 exact)

#define SCALE 0.17677669529663687f

__device__ __forceinline__ unsigned f2tf(float f) {
    unsigned r; asm("cvt.rna.tf32.f32 %0, %1;" : "=r"(r) : "f"(f)); return r;
}
__device__ __forceinline__ float tfbits(float f) {   // value -> tf32 bit pattern as float
    return __uint_as_float(f2tf(f));
}

__global__ void k_pre(const float* __restrict__ Wq, const float* __restrict__ bq,
                      const float* __restrict__ Wk,
                      const float* __restrict__ Wv, const float* __restrict__ Wo,
                      const float* __restrict__ Wse1, const float* __restrict__ Wse2)
{
    int i = blockIdx.x * 256 + threadIdx.x;
    if (i < 16384) {
        int a = i >> 7, b = i & 127;
        g_WqT[i] = tfbits(Wq[b*128 + a] * SCALE);
        g_WkN[i] = tfbits(Wk[i]);
        g_WvT[i] = tfbits(Wv[b*128 + a]);
        int j = a, oc = b;
        g_WoP[i] = tfbits(Wo[oc*128 + ((j & 31)*4 + (j >> 5))]);
    }
    if (i < 4096) {
        int oc1 = i >> 5, i1 = i & 31;
        g_Se1T[i] = tfbits(Wse1[i1*128 + oc1]);
        int i2 = i >> 7, oc2 = i & 127;
        g_Se2T[i] = tfbits(Wse2[oc2*32 + i2]);
    }
    if (i < 128) g_bqs[i] = bq[i] * SCALE;
}

// ---------------- helpers ----------------
__device__ __forceinline__ u64 pk2(float lo, float hi) {
    u64 r; asm("mov.b64 %0, {%1, %2};" : "=l"(r) : "f"(lo), "f"(hi)); return r;
}
__device__ __forceinline__ void upk(u64 v, float& lo, float& hi) {
    asm("mov.b64 {%0, %1}, %2;" : "=f"(lo), "=f"(hi) : "l"(v));
}
__device__ __forceinline__ u64 fma2(u64 a, u64 b, u64 c) {
    u64 d; asm("fma.rn.f32x2 %0, %1, %2, %3;" : "=l"(d) : "l"(a), "l"(b), "l"(c)); return d;
}
__device__ __forceinline__ u64 add2(u64 a, u64 b) {
    u64 d; asm("add.rn.f32x2 %0, %1, %2;" : "=l"(d) : "l"(a), "l"(b)); return d;
}
__device__ __forceinline__ void mma8(float d[4], const unsigned a[4],
                                     unsigned b0, unsigned b1) {
    asm volatile(
        "mma.sync.aligned.m16n8k8.row.col.f32.tf32.tf32.f32 "
        "{%0,%1,%2,%3}, {%4,%5,%6,%7}, {%8,%9}, {%0,%1,%2,%3};"
        : "+f"(d[0]), "+f"(d[1]), "+f"(d[2]), "+f"(d[3])
        : "r"(a[0]), "r"(a[1]), "r"(a[2]), "r"(a[3]), "r"(b0), "r"(b1));
}
__device__ __forceinline__ void cpa16(unsigned dst, const void* src) {
    asm volatile("cp.async.cg.shared.global [%0], [%1], 16;" :: "r"(dst), "l"(src));
}
__device__ __forceinline__ void cp_commit() { asm volatile("cp.async.commit_group;"); }
__device__ __forceinline__ void cp_waitall() { asm volatile("cp.async.wait_group 0;" ::: "memory"); }
__device__ __forceinline__ float sigm(float z) { return 1.0f / (1.0f + __expf(-z)); }

// ---------------- smem layout (floats), 32 rows/block, 1024 threads ----------------
#define W1   0        // 17408: WqT[c][j](136) -> WvT(136) -> [Se1T(40) | Se2T(136)@+5120 | Wg@+9472]
#define W2   17408    // 17408: WkN[j][c](136) -> WoP[j][oc](136)
#define QR   34816    // 4224:  q[r][132](tf32) -> attn[row][80](fp32) -> o[r][132](tf32) -> T1[r][36](tf32)
#define QK   39040    // 16512: x[r][132](tf32) -> qk[r][516](fp32) -> ctx[r][516](tf32) -> o2[r][132](fp32)
#define GG   (QR + 2560)
#define SMEM_FLOATS 55552    // 222208 B

__global__ void __launch_bounds__(1024, 1) k_fused(
    const float* __restrict__ x,
    const float* __restrict__ nb,
    const float* __restrict__ bv, const float* __restrict__ bo,
    const float* __restrict__ Wg, const float* __restrict__ bg,
    float* __restrict__ out)
{
    extern __shared__ float sm[];
    const int t = threadIdx.x;
    const int lane = t & 31;
    const int w = t >> 5;               // warp 0..31
    const int gid = lane >> 2;          // mma group id (row-ish)
    const int tig = lane & 3;           // thread-in-group (col-ish)
    const long rowBase = (long)blockIdx.x * 32;
    unsigned sb = (unsigned)__cvta_generic_to_shared(sm);

    // ============ phase 0: Wq->W1, Wk->W2 (cp.async); x -> QK as tf32 bits ============
    #pragma unroll
    for (int i = t; i < 4096; i += 1024)
        cpa16(sb + (W1 + (i>>5)*136 + (i&31)*4)*4, g_WqT + i*4);
    #pragma unroll
    for (int i = t; i < 4096; i += 1024)
        cpa16(sb + (W2 + (i>>5)*136 + (i&31)*4)*4, g_WkN + i*4);
    cp_commit();
    {
        const float4* xg = (const float4*)x + rowBase*32;
        int r = t >> 5, c4 = t & 31;
        float4 v = xg[t];
        float4 tv = make_float4(tfbits(v.x), tfbits(v.y), tfbits(v.z), tfbits(v.w));
        *(float4*)&sm[QK + r*132 + c4*4] = tv;
    }
    cp_waitall();
    __syncthreads();

    // ============ stage A (mma, split-k x2): q = s*(Wq x + bq) -> QR tf32 ============
    {
        const int mt = w & 1, kh = (w >> 1) & 1, ng = w >> 2;   // ng 0..7
        const int r0 = mt * 16;
        float acc[2][4];
        #pragma unroll
        for (int nt = 0; nt < 2; nt++)
            #pragma unroll
            for (int p = 0; p < 4; p++) acc[nt][p] = 0.0f;
        #pragma unroll 4
        for (int kk = 0; kk < 8; kk++) {
            const int c0 = kh*64 + kk*8;
            unsigned a[4];
            a[0] = __float_as_uint(sm[QK + (r0+gid  )*132 + c0 + tig]);
            a[1] = __float_as_uint(sm[QK + (r0+gid+8)*132 + c0 + tig]);
            a[2] = __float_as_uint(sm[QK + (r0+gid  )*132 + c0 + tig + 4]);
            a[3] = __float_as_uint(sm[QK + (r0+gid+8)*132 + c0 + tig + 4]);
            #pragma unroll
            for (int nt = 0; nt < 2; nt++) {
                const int n0 = ng*16 + nt*8;
                unsigned b0 = __float_as_uint(sm[W1 + (c0+tig  )*136 + n0 + gid]);
                unsigned b1 = __float_as_uint(sm[W1 + (c0+tig+4)*136 + n0 + gid]);
                mma8(acc[nt], a, b0, b1);
            }
        }
        if (kh == 1) {
            #pragma unroll
            for (int nt = 0; nt < 2; nt++) {
                const int base = QR + (r0+gid)*132 + ng*16 + nt*8 + 2*tig;
                *(u64*)&sm[base]         = pk2(acc[nt][0], acc[nt][1]);
                *(u64*)&sm[base + 8*132] = pk2(acc[nt][2], acc[nt][3]);
            }
        }
        __syncthreads();
        if (kh == 0) {
            #pragma unroll
            for (int nt = 0; nt < 2; nt++) {
                const int n0 = ng*16 + nt*8;
                float bj0 = __ldg(&g_bqs[n0 + 2*tig]);
                float bj1 = __ldg(&g_bqs[n0 + 2*tig + 1]);
                const int base = QR + (r0+gid)*132 + n0 + 2*tig;
                float l0, h0, l1, h1;
                upk(*(const u64*)&sm[base], l0, h0);
                upk(*(const u64*)&sm[base + 8*132], l1, h1);
                *(u64*)&sm[base] =
                    pk2(tfbits(acc[nt][0] + l0 + bj0), tfbits(acc[nt][1] + h0 + bj1));
                *(u64*)&sm[base + 8*132] =
                    pk2(tfbits(acc[nt][2] + l1 + bj0), tfbits(acc[nt][3] + h1 + bj1));
            }
        }
    }
    __syncthreads();
    // W1 free -> prefetch WvT
    #pragma unroll
    for (int i = t; i < 4096; i += 1024)
        cpa16(sb + (W1 + (i>>5)*136 + (i&31)*4)*4, g_WvT + i*4);
    cp_commit();

    // ============ stage B (mma): qk[r][512] -> QK fp32 (over x) ============
    {
        const int mt = w & 1, ng = w >> 1;      // ng 0..15 -> 32 qk-cols each
        const int r0 = mt * 16;
        const int h = ng >> 2;                  // head
        const int nb0 = ng * 32;                // global qk col base
        const int cl0 = (ng & 3) * 32;          // head-local Wk col base
        float acc[4][4];
        #pragma unroll
        for (int i = 0; i < 4; i++)
            #pragma unroll
            for (int p = 0; p < 4; p++) acc[i][p] = 0.0f;
        #pragma unroll
        for (int kk = 0; kk < 4; kk++) {
            const int jc = h*32 + kk*8;
            unsigned a[4];
            a[0] = __float_as_uint(sm[QR + (r0+gid  )*132 + jc + tig]);
            a[1] = __float_as_uint(sm[QR + (r0+gid+8)*132 + jc + tig]);
            a[2] = __float_as_uint(sm[QR + (r0+gid  )*132 + jc + tig + 4]);
            a[3] = __float_as_uint(sm[QR + (r0+gid+8)*132 + jc + tig + 4]);
            #pragma unroll
            for (int i = 0; i < 4; i++) {
                const int cl = cl0 + i*8;
                unsigned b0 = __float_as_uint(sm[W2 + (jc+tig  )*136 + cl + gid]);
                unsigned b1 = __float_as_uint(sm[W2 + (jc+tig+4)*136 + cl + gid]);
                mma8(acc[i], a, b0, b1);
            }
        }
        __syncthreads();     // all stage-A/B reads of QK(x)/QR(q) complete
        #pragma unroll
        for (int i = 0; i < 4; i++) {
            const int base = QK + (r0+gid)*516 + nb0 + i*8 + 2*tig;
            *(u64*)&sm[base]         = pk2(acc[i][0], acc[i][1]);
            *(u64*)&sm[base + 8*516] = pk2(acc[i][2], acc[i][3]);
        }
    }
    __syncthreads();
    // W2 free -> prefetch WoP
    #pragma unroll
    for (int i = t; i < 4096; i += 1024)
        cpa16(sb + (W2 + (i>>5)*136 + (i&31)*4)*4, g_WoP + i*4);
    cp_commit();

    // ============ stage C1+C2: scores + softmax (warp = row, exact fp32) ============
    {
        const int row = w;
        const int n = (lane < 20) ? lane : 19;
        const float* nbr = nb + (((rowBase + row)*20 + n) << 7);
        const float* qkr = sm + QK + row*516;
        u64 acc[4][2];
        #pragma unroll
        for (int h = 0; h < 4; h++) { acc[h][0] = 0ull; acc[h][1] = 0ull; }
        #pragma unroll 4
        for (int c4 = 0; c4 < 32; c4++) {
            float4 v = *(const float4*)(nbr + c4*4);
            u64 v01 = pk2(v.x, v.y), v23 = pk2(v.z, v.w);
            #pragma unroll
            for (int h = 0; h < 4; h++) {
                float4 qv = *(const float4*)(qkr + h*128 + c4*4);
                acc[h][0] = fma2(pk2(qv.x, qv.y), v01, acc[h][0]);
                acc[h][1] = fma2(pk2(qv.z, qv.w), v23, acc[h][1]);
            }
        }
        float sc[4];
        #pragma unroll
        for (int h = 0; h < 4; h++) {
            u64 s2 = add2(acc[h][0], acc[h][1]);
            float lo, hi; upk(s2, lo, hi);
            sc[h] = (lane < 20) ? (lo + hi) : -1e30f;
        }
        float m[4];
        #pragma unroll
        for (int h = 0; h < 4; h++) m[h] = sc[h];
        #pragma unroll
        for (int o = 16; o; o >>= 1) {
            #pragma unroll
            for (int h = 0; h < 4; h++)
                m[h] = fmaxf(m[h], __shfl_xor_sync(0xffffffffu, m[h], o));
        }
        float e[4], s[4];
        #pragma unroll
        for (int h = 0; h < 4; h++) { e[h] = __expf(sc[h] - m[h]); s[h] = e[h]; }
        #pragma unroll
        for (int o = 16; o; o >>= 1) {
            #pragma unroll
            for (int h = 0; h < 4; h++)
                s[h] += __shfl_xor_sync(0xffffffffu, s[h], o);
        }
        if (lane < 20)
            *(float4*)&sm[QR + row*80 + lane*4] =
                make_float4(e[0]/s[0], e[1]/s[1], e[2]/s[2], e[3]/s[3]);
    }
    __syncwarp();

    // ============ stage C3: ctx -> QK as tf32 bits (row warp-private) ============
    {
        const int row = w;
        const float* nbr = nb + ((rowBase + row)*20 << 7);
        u64 acc[4][2];
        #pragma unroll
        for (int ch = 0; ch < 4; ch++) { acc[ch][0] = 0ull; acc[ch][1] = 0ull; }
        #pragma unroll 4
        for (int n = 0; n < 20; n++) {
            float4 at = *(const float4*)&sm[QR + row*80 + n*4];
            u64 a01 = pk2(at.x, at.y), a23 = pk2(at.z, at.w);
            #pragma unroll
            for (int ch = 0; ch < 4; ch++) {
                float v = __ldg(nbr + n*128 + ch*32 + lane);
                u64 vp = pk2(v, v);
                acc[ch][0] = fma2(a01, vp, acc[ch][0]);
                acc[ch][1] = fma2(a23, vp, acc[ch][1]);
            }
        }
        #pragma unroll
        for (int ch = 0; ch < 4; ch++) {
            const int c = ch*32 + lane;
            float v0, v1, v2, v3;
            upk(acc[ch][0], v0, v1);
            upk(acc[ch][1], v2, v3);
            sm[QK + row*516 +   0 + c] = tfbits(v0);
            sm[QK + row*516 + 128 + c] = tfbits(v1);
            sm[QK + row*516 + 256 + c] = tfbits(v2);
            sm[QK + row*516 + 384 + c] = tfbits(v3);
        }
    }
    cp_waitall();          // WvT / WoP landed
    __syncthreads();

    // ============ stage D (mma, split-k x2): o = Wv ctx + bv -> QR tf32 ============
    {
        const int mt = w & 1, kh = (w >> 1) & 1, ng = w >> 2;   // ng 0..7
        const int r0 = mt * 16;
        const int h = ng >> 1;                  // head of the j-range ng*16..+15
        float acc[2][4];
        #pragma unroll
        for (int nt = 0; nt < 2; nt++)
            #pragma unroll
            for (int p = 0; p < 4; p++) acc[nt][p] = 0.0f;
        #pragma unroll 4
        for (int kk = 0; kk < 8; kk++) {
            const int c0 = kh*64 + kk*8;        // head-local c
            unsigned a[4];
            a[0] = __float_as_uint(sm[QK + (r0+gid  )*516 + h*128 + c0 + tig]);
            a[1] = __float_as_uint(sm[QK + (r0+gid+8)*516 + h*128 + c0 + tig]);
            a[2] = __float_as_uint(sm[QK + (r0+gid  )*516 + h*128 + c0 + tig + 4]);
            a[3] = __float_as_uint(sm[QK + (r0+gid+8)*516 + h*128 + c0 + tig + 4]);
            #pragma unroll
            for (int nt = 0; nt < 2; nt++) {
                const int n0 = ng*16 + nt*8;    // global j
                unsigned b0 = __float_as_uint(sm[W1 + (c0+tig  )*136 + n0 + gid]);
                unsigned b1 = __float_as_uint(sm[W1 + (c0+tig+4)*136 + n0 + gid]);
                mma8(acc[nt], a, b0, b1);
            }
        }
        if (kh == 1) {
            #pragma unroll
            for (int nt = 0; nt < 2; nt++) {
                const int base = QR + (r0+gid)*132 + ng*16 + nt*8 + 2*tig;
                *(u64*)&sm[base]         = pk2(acc[nt][0], acc[nt][1]);
                *(u64*)&sm[base + 8*132] = pk2(acc[nt][2], acc[nt][3]);
            }
        }
        __syncthreads();
        if (kh == 0) {
            #pragma unroll
            for (int nt = 0; nt < 2; nt++) {
                const int n0 = ng*16 + nt*8;
                float bj0 = __ldg(&bv[n0 + 2*tig]);
                float bj1 = __ldg(&bv[n0 + 2*tig + 1]);
                const int base = QR + (r0+gid)*132 + n0 + 2*tig;
                float l0, h0v, l1, h1v;
                upk(*(const u64*)&sm[base], l0, h0v);
                upk(*(const u64*)&sm[base + 8*132], l1, h1v);
                *(u64*)&sm[base] =
                    pk2(tfbits(acc[nt][0] + l0 + bj0), tfbits(acc[nt][1] + h0v + bj1));
                *(u64*)&sm[base + 8*132] =
                    pk2(tfbits(acc[nt][2] + l1 + bj0), tfbits(acc[nt][3] + h1v + bj1));
            }
        }
    }
    __syncthreads();
    // W1 free -> prefetch SE weights + Wg
    #pragma unroll
    for (int i = t; i < 1024; i += 1024)
        cpa16(sb + (W1 + (i>>3)*40 + (i&7)*4)*4, g_Se1T + i*4);
    #pragma unroll
    for (int i = t; i < 1024; i += 1024)
        cpa16(sb + (W1 + 5120 + (i>>5)*136 + (i&31)*4)*4, g_Se2T + i*4);
    if (t < 64) cpa16(sb + (W1 + 9472 + t*4)*4, Wg + t*4);
    cp_commit();

    // ============ stage E (mma, split-k x2): o2 = WoP o + bo -> QK fp32 ============
    {
        const int mt = w & 1, kh = (w >> 1) & 1, ng = w >> 2;   // ng 0..7 (oc16 groups)
        const int r0 = mt * 16;
        float acc[2][4];
        #pragma unroll
        for (int nt = 0; nt < 2; nt++)
            #pragma unroll
            for (int p = 0; p < 4; p++) acc[nt][p] = 0.0f;
        #pragma unroll 4
        for (int kk = 0; kk < 8; kk++) {
            const int j0 = kh*64 + kk*8;
            unsigned a[4];
            a[0] = __float_as_uint(sm[QR + (r0+gid  )*132 + j0 + tig]);
            a[1] = __float_as_uint(sm[QR + (r0+gid+8)*132 + j0 + tig]);
            a[2] = __float_as_uint(sm[QR + (r0+gid  )*132 + j0 + tig + 4]);
            a[3] = __float_as_uint(sm[QR + (r0+gid+8)*132 + j0 + tig + 4]);
            #pragma unroll
            for (int nt = 0; nt < 2; nt++) {
                const int n0 = ng*16 + nt*8;
                unsigned b0 = __float_as_uint(sm[W2 + (j0+tig  )*136 + n0 + gid]);
                unsigned b1 = __float_as_uint(sm[W2 + (j0+tig+4)*136 + n0 + gid]);
                mma8(acc[nt], a, b0, b1);
            }
        }
        __syncthreads();     // all E reads done; QK(ctx) may now be overwritten
        if (kh == 1) {
            #pragma unroll
            for (int nt = 0; nt < 2; nt++) {
                const int base = QK + (r0+gid)*132 + ng*16 + nt*8 + 2*tig;
                *(u64*)&sm[base]         = pk2(acc[nt][0], acc[nt][1]);
                *(u64*)&sm[base + 8*132] = pk2(acc[nt][2], acc[nt][3]);
            }
        }
        __syncthreads();
        if (kh == 0) {
            #pragma unroll
            for (int nt = 0; nt < 2; nt++) {
                const int n0 = ng*16 + nt*8;
                float bj0 = __ldg(&bo[n0 + 2*tig]);
                float bj1 = __ldg(&bo[n0 + 2*tig + 1]);
                const int base = QK + (r0+gid)*132 + n0 + 2*tig;
                float l0, h0v, l1, h1v;
                upk(*(const u64*)&sm[base], l0, h0v);
                upk(*(const u64*)&sm[base + 8*132], l1, h1v);
                *(u64*)&sm[base] =
                    pk2(acc[nt][0] + l0 + bj0, acc[nt][1] + h0v + bj1);   // fp32
                *(u64*)&sm[base + 8*132] =
                    pk2(acc[nt][2] + l1 + bj0, acc[nt][3] + h1v + bj1);
            }
        }
    }
    cp_waitall();          // SE weights landed
    __syncthreads();

    // ============ stage F (mma, 16 warps, split-k x2): T1 = relu(Se1.o2) -> QR tf32 ============
    if (w < 16) {
        const int mt = w & 1, nt = (w >> 1) & 3, kh = w >> 3;   // nt 0..3, kh 0..1
        const int r0 = mt * 16, n0 = nt * 8;
        float acc[4] = {0.f, 0.f, 0.f, 0.f};
        #pragma unroll 4
        for (int kk = 0; kk < 8; kk++) {
            const int k0 = kh*64 + kk*8;
            unsigned a[4];
            a[0] = f2tf(sm[QK + (r0+gid  )*132 + k0 + tig]);
            a[1] = f2tf(sm[QK + (r0+gid+8)*132 + k0 + tig]);
            a[2] = f2tf(sm[QK + (r0+gid  )*132 + k0 + tig + 4]);
            a[3] = f2tf(sm[QK + (r0+gid+8)*132 + k0 + tig + 4]);
            unsigned b0 = __float_as_uint(sm[W1 + (k0+tig  )*40 + n0 + gid]);
            unsigned b1 = __float_as_uint(sm[W1 + (k0+tig+4)*40 + n0 + gid]);
            mma8(acc, a, b0, b1);
        }
        const int base = QR + (r0+gid)*36 + n0 + 2*tig;
        if (kh == 1) {
            *(u64*)&sm[base]        = pk2(acc[0], acc[1]);
            *(u64*)&sm[base + 8*36] = pk2(acc[2], acc[3]);
        }
        __syncthreads();
        if (kh == 0) {
            float l0, h0v, l1, h1v;
            upk(*(const u64*)&sm[base], l0, h0v);
            upk(*(const u64*)&sm[base + 8*36], l1, h1v);
            *(u64*)&sm[base] =
                pk2(tfbits(fmaxf(acc[0]+l0, 0.f)), tfbits(fmaxf(acc[1]+h0v, 0.f)));
            *(u64*)&sm[base + 8*36] =
                pk2(tfbits(fmaxf(acc[2]+l1, 0.f)), tfbits(fmaxf(acc[3]+h1v, 0.f)));
        }
    } else {
        __syncthreads();    // match F's internal barrier
    }
    __syncthreads();

    // ============ stage G (mma): o2 *= sigmoid(Se2 . T1) in place ============
    {
        const int mt = w & 1, nt = w >> 1;
        const int r0 = mt * 16, n0 = nt * 8;
        float acc[4] = {0.f, 0.f, 0.f, 0.f};
        #pragma unroll
        for (int kk = 0; kk < 4; kk++) {
            const int i0 = kk*8;
            unsigned a[4];
            a[0] = __float_as_uint(sm[QR + (r0+gid  )*36 + i0 + tig]);
            a[1] = __float_as_uint(sm[QR + (r0+gid+8)*36 + i0 + tig]);
            a[2] = __float_as_uint(sm[QR + (r0+gid  )*36 + i0 + tig + 4]);
            a[3] = __float_as_uint(sm[QR + (r0+gid+8)*36 + i0 + tig + 4]);
            unsigned b0 = __float_as_uint(sm[W1 + 5120 + (i0+tig  )*136 + n0 + gid]);
            unsigned b1 = __float_as_uint(sm[W1 + 5120 + (i0+tig+4)*136 + n0 + gid]);
            mma8(acc, a, b0, b1);
        }
        const int b0a = QK + (r0+gid)*132 + n0 + 2*tig;
        const int b1a = b0a + 8*132;
        float lo, hi;
        u64 v = *(const u64*)&sm[b0a]; upk(v, lo, hi);
        *(u64*)&sm[b0a] = pk2(lo * sigm(acc[0]), hi * sigm(acc[1]));
        v = *(const u64*)&sm[b1a]; upk(v, lo, hi);
        *(u64*)&sm[b1a] = pk2(lo * sigm(acc[2]), hi * sigm(acc[3]));
    }
    __syncthreads();

    // ============ stage H: residual gate (warp = row; x from L2-hot gmem) ============
    {
        const float bgv = __ldg(bg);
        const int row = w;
        const float* xr = x + (rowBase + row)*128;
        float p = 0.0f;
        #pragma unroll
        for (int k = 0; k < 4; k++) {
            const int cx = lane + 32*k;
            p += sm[W1 + 9472 + cx]       * __ldg(xr + cx);
            p += sm[W1 + 9472 + 128 + cx] * sm[QK + row*132 + cx];
        }
        #pragma unroll
        for (int o = 16; o; o >>= 1) p += __shfl_xor_sync(0xffffffffu, p, o);
        if (lane == 0) sm[GG + row] = sigm(p + bgv);
    }
    __syncthreads();

    // ============ stage I: out = g*o3 + (1-g)*x ============
    {
        const float4* xg = (const float4*)x + rowBase*32;
        float4* og4 = (float4*)out + rowBase*32;
        const int r = t >> 5, c4 = t & 31;
        const float g = sm[GG + r];
        float4 xv = __ldg(&xg[t]);
        float4 ov = *(const float4*)&sm[QK + r*132 + c4*4];
        float4 res;
        res.x = g*ov.x + (1.0f-g)*xv.x;
        res.y = g*ov.y + (1.0f-g)*xv.y;
        res.z = g*ov.z + (1.0f-g)*xv.z;
        res.w = g*ov.w + (1.0f-g)*xv.w;
        og4[t] = res;
    }
}

// =======================================================================
extern "C" void kernel_launch(void* const* d_in, const int* in_sizes, int n_in,
                              void* d_out, int out_size)
{
    const float* x    = (const float*)d_in[0];
    const float* nb   = (const float*)d_in[1];
    const float* Wq   = (const float*)d_in[2];
    const float* bq   = (const float*)d_in[3];
    const float* Wk   = (const float*)d_in[4];
    // d_in[5] = bk : constant over n => softmax-invariant, unused
    const float* Wv   = (const float*)d_in[6];
    const float* bv   = (const float*)d_in[7];
    const float* Wo   = (const float*)d_in[8];
    const float* bo   = (const float*)d_in[9];
    const float* Wse1 = (const float*)d_in[10];
    const float* Wse2 = (const float*)d_in[11];
    const float* Wg   = (const float*)d_in[12];
    const float* bg   = (const float*)d_in[13];
    float* out = (float*)d_out;

    cudaFuncSetAttribute(k_fused, cudaFuncAttributeMaxDynamicSharedMemorySize,
                         SMEM_FLOATS * 4);

    k_pre<<<64, 256>>>(Wq, bq, Wk, Wv, Wo, Wse1, Wse2);
    k_fused<<<2048, 1024, SMEM_FLOATS * 4>>>(x, nb, bv, bo, Wg, bg, out);
}

// round 16
// speedup vs baseline: 1.0650x; 1.0650x over previous
#include <cuda_runtime.h>
#include <math.h>

typedef unsigned long long u64;

// ---------------- pretransposed tf32 weights (device scratch) ----------------
__device__ float g_WqT[16384];   // [c][j]  = tf32(Wq[j][c] * 1/sqrt(32))
__device__ float g_WkN[16384];   // [j][c]  = tf32(Wk[j][c])
__device__ float g_WvT[16384];   // [c][j]  = tf32(Wv[j][c])
__device__ float g_WoP[16384];   // [j][oc] = tf32(Wo[oc][(j&31)*4 + (j>>5)])
__device__ float g_Se1T[4096];   // [oc][i] = tf32(Wse1[i][oc])
__device__ float g_Se2T[4096];   // [i][oc] = tf32(Wse2[oc][i])
__device__ float g_bqs[128];     // bq * 1/sqrt(32)  (fp32 exact)

#define SCALE 0.17677669529663687f

__device__ __forceinline__ unsigned f2tf(float f) {
    unsigned r; asm("cvt.rna.tf32.f32 %0, %1;" : "=r"(r) : "f"(f)); return r;
}
__device__ __forceinline__ float tfbits(float f) {   // value -> tf32 bit pattern as float
    return __uint_as_float(f2tf(f));
}

__global__ void k_pre(const float* __restrict__ Wq, const float* __restrict__ bq,
                      const float* __restrict__ Wk,
                      const float* __restrict__ Wv, const float* __restrict__ Wo,
                      const float* __restrict__ Wse1, const float* __restrict__ Wse2)
{
    int i = blockIdx.x * 256 + threadIdx.x;
    if (i < 16384) {
        int a = i >> 7, b = i & 127;
        g_WqT[i] = tfbits(Wq[b*128 + a] * SCALE);
        g_WkN[i] = tfbits(Wk[i]);
        g_WvT[i] = tfbits(Wv[b*128 + a]);
        int j = a, oc = b;
        g_WoP[i] = tfbits(Wo[oc*128 + ((j & 31)*4 + (j >> 5))]);
    }
    if (i < 4096) {
        int oc1 = i >> 5, i1 = i & 31;
        g_Se1T[i] = tfbits(Wse1[i1*128 + oc1]);
        int i2 = i >> 7, oc2 = i & 127;
        g_Se2T[i] = tfbits(Wse2[oc2*32 + i2]);
    }
    if (i < 128) g_bqs[i] = bq[i] * SCALE;
}

// ---------------- helpers ----------------
__device__ __forceinline__ u64 pk2(float lo, float hi) {
    u64 r; asm("mov.b64 %0, {%1, %2};" : "=l"(r) : "f"(lo), "f"(hi)); return r;
}
__device__ __forceinline__ void upk(u64 v, float& lo, float& hi) {
    asm("mov.b64 {%0, %1}, %2;" : "=f"(lo), "=f"(hi) : "l"(v));
}
__device__ __forceinline__ u64 fma2(u64 a, u64 b, u64 c) {
    u64 d; asm("fma.rn.f32x2 %0, %1, %2, %3;" : "=l"(d) : "l"(a), "l"(b), "l"(c)); return d;
}
__device__ __forceinline__ u64 add2(u64 a, u64 b) {
    u64 d; asm("add.rn.f32x2 %0, %1, %2;" : "=l"(d) : "l"(a), "l"(b)); return d;
}
__device__ __forceinline__ void mma8(float d[4], const unsigned a[4],
                                     unsigned b0, unsigned b1) {
    asm volatile(
        "mma.sync.aligned.m16n8k8.row.col.f32.tf32.tf32.f32 "
        "{%0,%1,%2,%3}, {%4,%5,%6,%7}, {%8,%9}, {%0,%1,%2,%3};"
        : "+f"(d[0]), "+f"(d[1]), "+f"(d[2]), "+f"(d[3])
        : "r"(a[0]), "r"(a[1]), "r"(a[2]), "r"(a[3]), "r"(b0), "r"(b1));
}
__device__ __forceinline__ void cpa16(unsigned dst, const void* src) {
    asm volatile("cp.async.cg.shared.global [%0], [%1], 16;" :: "r"(dst), "l"(src));
}
__device__ __forceinline__ void cp_commit() { asm volatile("cp.async.commit_group;"); }
__device__ __forceinline__ void cp_waitall() { asm volatile("cp.async.wait_group 0;" ::: "memory"); }
__device__ __forceinline__ float sigm(float z) { return 1.0f / (1.0f + __expf(-z)); }

// ---------------- smem layout (floats), 32 rows/block, 1024 threads ----------------
// Weight buffers padded to 136 (B-frag bank-conflict-free)
#define W1   0        // 17408: WqT[c][j](136) -> WvT(136) -> [Se1T(40) | Se2T(136)@+5120 | Wg@+9472]
#define W2   17408    // 17408: WkN[j][c](136) -> WoP[j][oc](136)
#define QR   34816    // 4224:  q[r][132](tf32) -> attn[row][80](fp32) -> o[r][132](tf32) -> T1[r][36](tf32)
#define QK   39040    // 16512: x[r][132](tf32) -> qk[r][516](fp32) -> ctx[r][516](tf32) -> o2[r][132](fp32)
#define GG   (QR + 2560)
#define SMEM_FLOATS 55552    // 222208 B

__global__ void __launch_bounds__(1024, 1) k_fused(
    const float* __restrict__ x,
    const float* __restrict__ nb,
    const float* __restrict__ bv, const float* __restrict__ bo,
    const float* __restrict__ Wg, const float* __restrict__ bg,
    float* __restrict__ out)
{
    extern __shared__ float sm[];
    const int t = threadIdx.x;
    const int lane = t & 31;
    const int w = t >> 5;               // warp 0..31
    const int gid = lane >> 2;          // mma group id (row-ish)
    const int tig = lane & 3;           // thread-in-group (col-ish)
    const long rowBase = (long)blockIdx.x * 32;
    unsigned sb = (unsigned)__cvta_generic_to_shared(sm);

    // ============ phase 0: Wq->W1, Wk->W2 (cp.async); x -> QK as tf32 bits ============
    #pragma unroll
    for (int i = t; i < 4096; i += 1024)
        cpa16(sb + (W1 + (i>>5)*136 + (i&31)*4)*4, g_WqT + i*4);
    #pragma unroll
    for (int i = t; i < 4096; i += 1024)
        cpa16(sb + (W2 + (i>>5)*136 + (i&31)*4)*4, g_WkN + i*4);
    cp_commit();
    {
        const float4* xg = (const float4*)x + rowBase*32;
        int r = t >> 5, c4 = t & 31;
        float4 v = xg[t];
        *(float4*)&sm[QK + r*132 + c4*4] =
            make_float4(tfbits(v.x), tfbits(v.y), tfbits(v.z), tfbits(v.w));
    }
    cp_waitall();
    __syncthreads();

    // ============ stage A (mma): q = s*(Wq x + bq) -> QR tf32 ============
    {
        const int mt = w & 1, ng = w >> 1;      // ng 0..15
        const int r0 = mt * 16, n0 = ng * 8;
        float acc[4] = {0.f, 0.f, 0.f, 0.f};
        #pragma unroll 4
        for (int kk = 0; kk < 16; kk++) {
            const int c0 = kk*8;
            unsigned a[4];
            a[0] = __float_as_uint(sm[QK + (r0+gid  )*132 + c0 + tig]);
            a[1] = __float_as_uint(sm[QK + (r0+gid+8)*132 + c0 + tig]);
            a[2] = __float_as_uint(sm[QK + (r0+gid  )*132 + c0 + tig + 4]);
            a[3] = __float_as_uint(sm[QK + (r0+gid+8)*132 + c0 + tig + 4]);
            unsigned b0 = __float_as_uint(sm[W1 + (c0+tig  )*136 + n0 + gid]);
            unsigned b1 = __float_as_uint(sm[W1 + (c0+tig+4)*136 + n0 + gid]);
            mma8(acc, a, b0, b1);
        }
        float bj0 = __ldg(&g_bqs[n0 + 2*tig]);
        float bj1 = __ldg(&g_bqs[n0 + 2*tig + 1]);
        const int base = QR + (r0+gid)*132 + n0 + 2*tig;
        *(u64*)&sm[base]         = pk2(tfbits(acc[0]+bj0), tfbits(acc[1]+bj1));
        *(u64*)&sm[base + 8*132] = pk2(tfbits(acc[2]+bj0), tfbits(acc[3]+bj1));
    }
    __syncthreads();
    // W1 free -> prefetch WvT
    #pragma unroll
    for (int i = t; i < 4096; i += 1024)
        cpa16(sb + (W1 + (i>>5)*136 + (i&31)*4)*4, g_WvT + i*4);
    cp_commit();

    // ============ stage B (mma): qk[r][512] -> QK fp32 (over x) ============
    // Output col global = nb0 + i*8; Wk col is HEAD-LOCAL: cl0 + i*8.
    {
        const int mt = w & 1, ng = w >> 1;      // ng 0..15 -> 32 qk-cols each
        const int r0 = mt * 16;
        const int h = ng >> 2;                  // head
        const int nb0 = ng * 32;                // global qk col base
        const int cl0 = (ng & 3) * 32;          // head-local Wk col base
        float acc[4][4];
        #pragma unroll
        for (int i = 0; i < 4; i++)
            #pragma unroll
            for (int p = 0; p < 4; p++) acc[i][p] = 0.0f;
        #pragma unroll
        for (int kk = 0; kk < 4; kk++) {
            const int jc = h*32 + kk*8;
            unsigned a[4];
            a[0] = __float_as_uint(sm[QR + (r0+gid  )*132 + jc + tig]);
            a[1] = __float_as_uint(sm[QR + (r0+gid+8)*132 + jc + tig]);
            a[2] = __float_as_uint(sm[QR + (r0+gid  )*132 + jc + tig + 4]);
            a[3] = __float_as_uint(sm[QR + (r0+gid+8)*132 + jc + tig + 4]);
            #pragma unroll
            for (int i = 0; i < 4; i++) {
                const int cl = cl0 + i*8;       // head-local column into Wk
                unsigned b0 = __float_as_uint(sm[W2 + (jc+tig  )*136 + cl + gid]);
                unsigned b1 = __float_as_uint(sm[W2 + (jc+tig+4)*136 + cl + gid]);
                mma8(acc[i], a, b0, b1);
            }
        }
        __syncthreads();     // all stage-A/B reads of QK(x)/QR(q) complete
        #pragma unroll
        for (int i = 0; i < 4; i++) {
            const int base = QK + (r0+gid)*516 + nb0 + i*8 + 2*tig;
            *(u64*)&sm[base]         = pk2(acc[i][0], acc[i][1]);
            *(u64*)&sm[base + 8*516] = pk2(acc[i][2], acc[i][3]);
        }
    }
    __syncthreads();
    // W2 free -> prefetch WoP
    #pragma unroll
    for (int i = t; i < 4096; i += 1024)
        cpa16(sb + (W2 + (i>>5)*136 + (i&31)*4)*4, g_WoP + i*4);
    cp_commit();

    // ============ stage C1+C2: scores + softmax (warp = row, exact fp32) ============
    {
        const int row = w;
        const int n = (lane < 20) ? lane : 19;
        const float* nbr = nb + (((rowBase + row)*20 + n) << 7);
        const float* qkr = sm + QK + row*516;
        u64 acc[4][2];
        #pragma unroll
        for (int h = 0; h < 4; h++) { acc[h][0] = 0ull; acc[h][1] = 0ull; }
        #pragma unroll 4
        for (int c4 = 0; c4 < 32; c4++) {
            float4 v = *(const float4*)(nbr + c4*4);
            u64 v01 = pk2(v.x, v.y), v23 = pk2(v.z, v.w);
            #pragma unroll
            for (int h = 0; h < 4; h++) {
                float4 qv = *(const float4*)(qkr + h*128 + c4*4);
                acc[h][0] = fma2(pk2(qv.x, qv.y), v01, acc[h][0]);
                acc[h][1] = fma2(pk2(qv.z, qv.w), v23, acc[h][1]);
            }
        }
        float sc[4];
        #pragma unroll
        for (int h = 0; h < 4; h++) {
            u64 s2 = add2(acc[h][0], acc[h][1]);
            float lo, hi; upk(s2, lo, hi);
            sc[h] = (lane < 20) ? (lo + hi) : -1e30f;
        }
        float m[4];
        #pragma unroll
        for (int h = 0; h < 4; h++) m[h] = sc[h];
        #pragma unroll
        for (int o = 16; o; o >>= 1) {
            #pragma unroll
            for (int h = 0; h < 4; h++)
                m[h] = fmaxf(m[h], __shfl_xor_sync(0xffffffffu, m[h], o));
        }
        float e[4], s[4];
        #pragma unroll
        for (int h = 0; h < 4; h++) { e[h] = __expf(sc[h] - m[h]); s[h] = e[h]; }
        #pragma unroll
        for (int o = 16; o; o >>= 1) {
            #pragma unroll
            for (int h = 0; h < 4; h++)
                s[h] += __shfl_xor_sync(0xffffffffu, s[h], o);
        }
        if (lane < 20)
            *(float4*)&sm[QR + row*80 + lane*4] =
                make_float4(e[0]/s[0], e[1]/s[1], e[2]/s[2], e[3]/s[3]);
    }
    __syncwarp();

    // ============ stage C3: ctx -> QK as tf32 bits (row warp-private) ============
    {
        const int row = w;
        const float* nbr = nb + ((rowBase + row)*20 << 7);
        u64 acc[4][2];
        #pragma unroll
        for (int ch = 0; ch < 4; ch++) { acc[ch][0] = 0ull; acc[ch][1] = 0ull; }
        #pragma unroll 4
        for (int n = 0; n < 20; n++) {
            float4 at = *(const float4*)&sm[QR + row*80 + n*4];   // broadcast
            u64 a01 = pk2(at.x, at.y), a23 = pk2(at.z, at.w);
            #pragma unroll
            for (int ch = 0; ch < 4; ch++) {
                float v = __ldg(nbr + n*128 + ch*32 + lane);
                u64 vp = pk2(v, v);
                acc[ch][0] = fma2(a01, vp, acc[ch][0]);
                acc[ch][1] = fma2(a23, vp, acc[ch][1]);
            }
        }
        #pragma unroll
        for (int ch = 0; ch < 4; ch++) {
            const int c = ch*32 + lane;
            float v0, v1, v2, v3;
            upk(acc[ch][0], v0, v1);
            upk(acc[ch][1], v2, v3);
            sm[QK + row*516 +   0 + c] = tfbits(v0);
            sm[QK + row*516 + 128 + c] = tfbits(v1);
            sm[QK + row*516 + 256 + c] = tfbits(v2);
            sm[QK + row*516 + 384 + c] = tfbits(v3);
        }
    }
    cp_waitall();          // WvT / WoP landed
    __syncthreads();

    // ============ stage D (mma): o = Wv ctx + bv -> QR tf32 ============
    {
        const int mt = w & 1, nt = w >> 1;      // nt 0..15
        const int r0 = mt * 16, n0 = nt * 8;    // n0 = global j (Wv output)
        const int h = nt >> 2;                  // head of output j-range
        float acc[4] = {0.f, 0.f, 0.f, 0.f};
        #pragma unroll 4
        for (int kk = 0; kk < 16; kk++) {
            const int c0 = kk*8;
            unsigned a[4];
            a[0] = __float_as_uint(sm[QK + (r0+gid  )*516 + h*128 + c0 + tig]);
            a[1] = __float_as_uint(sm[QK + (r0+gid+8)*516 + h*128 + c0 + tig]);
            a[2] = __float_as_uint(sm[QK + (r0+gid  )*516 + h*128 + c0 + tig + 4]);
            a[3] = __float_as_uint(sm[QK + (r0+gid+8)*516 + h*128 + c0 + tig + 4]);
            unsigned b0 = __float_as_uint(sm[W1 + (c0+tig  )*136 + n0 + gid]);
            unsigned b1 = __float_as_uint(sm[W1 + (c0+tig+4)*136 + n0 + gid]);
            mma8(acc, a, b0, b1);
        }
        float bj0 = __ldg(&bv[n0 + 2*tig]);
        float bj1 = __ldg(&bv[n0 + 2*tig + 1]);
        const int base = QR + (r0+gid)*132 + n0 + 2*tig;
        *(u64*)&sm[base]         = pk2(tfbits(acc[0]+bj0), tfbits(acc[1]+bj1));
        *(u64*)&sm[base + 8*132] = pk2(tfbits(acc[2]+bj0), tfbits(acc[3]+bj1));
    }
    __syncthreads();
    // W1 free -> prefetch SE weights + Wg
    #pragma unroll
    for (int i = t; i < 1024; i += 1024)
        cpa16(sb + (W1 + (i>>3)*40 + (i&7)*4)*4, g_Se1T + i*4);
    #pragma unroll
    for (int i = t; i < 1024; i += 1024)
        cpa16(sb + (W1 + 5120 + (i>>5)*136 + (i&31)*4)*4, g_Se2T + i*4);
    if (t < 64) cpa16(sb + (W1 + 9472 + t*4)*4, Wg + t*4);
    cp_commit();

    // ============ stage E (mma): o2 = WoP o + bo -> QK fp32 (over ctx) ============
    {
        const int mt = w & 1, nt = w >> 1;
        const int r0 = mt * 16, n0 = nt * 8;
        float acc[4] = {0.f, 0.f, 0.f, 0.f};
        #pragma unroll 4
        for (int kk = 0; kk < 16; kk++) {
            const int j0 = kk*8;
            unsigned a[4];
            a[0] = __float_as_uint(sm[QR + (r0+gid  )*132 + j0 + tig]);
            a[1] = __float_as_uint(sm[QR + (r0+gid+8)*132 + j0 + tig]);
            a[2] = __float_as_uint(sm[QR + (r0+gid  )*132 + j0 + tig + 4]);
            a[3] = __float_as_uint(sm[QR + (r0+gid+8)*132 + j0 + tig + 4]);
            unsigned b0 = __float_as_uint(sm[W2 + (j0+tig  )*136 + n0 + gid]);
            unsigned b1 = __float_as_uint(sm[W2 + (j0+tig+4)*136 + n0 + gid]);
            mma8(acc, a, b0, b1);
        }
        __syncthreads();     // all E reads of ctx (QK) done before o2 overwrites
        float bj0 = __ldg(&bo[n0 + 2*tig]);
        float bj1 = __ldg(&bo[n0 + 2*tig + 1]);
        const int base = QK + (r0+gid)*132 + n0 + 2*tig;
        *(u64*)&sm[base]         = pk2(acc[0]+bj0, acc[1]+bj1);
        *(u64*)&sm[base + 8*132] = pk2(acc[2]+bj0, acc[3]+bj1);
    }
    cp_waitall();          // SE weights landed
    __syncthreads();

    // ============ stage F (mma, 8 warps): T1 = relu(Se1 . o2) -> QR tf32 ============
    if (w < 8) {
        const int mt = w & 1, nt = w >> 1;      // nt 0..3
        const int r0 = mt * 16, n0 = nt * 8;
        float acc[4] = {0.f, 0.f, 0.f, 0.f};
        #pragma unroll 4
        for (int kk = 0; kk < 16; kk++) {
            const int k0 = kk*8;
            unsigned a[4];
            a[0] = f2tf(sm[QK + (r0+gid  )*132 + k0 + tig]);
            a[1] = f2tf(sm[QK + (r0+gid+8)*132 + k0 + tig]);
            a[2] = f2tf(sm[QK + (r0+gid  )*132 + k0 + tig + 4]);
            a[3] = f2tf(sm[QK + (r0+gid+8)*132 + k0 + tig + 4]);
            unsigned b0 = __float_as_uint(sm[W1 + (k0+tig  )*40 + n0 + gid]);
            unsigned b1 = __float_as_uint(sm[W1 + (k0+tig+4)*40 + n0 + gid]);
            mma8(acc, a, b0, b1);
        }
        const int base = QR + (r0+gid)*36 + n0 + 2*tig;
        *(u64*)&sm[base] =
            pk2(tfbits(fmaxf(acc[0],0.f)), tfbits(fmaxf(acc[1],0.f)));
        *(u64*)&sm[base + 8*36] =
            pk2(tfbits(fmaxf(acc[2],0.f)), tfbits(fmaxf(acc[3],0.f)));
    }
    __syncthreads();

    // ============ stage G (mma): o2 *= sigmoid(Se2 . T1) in place ============
    {
        const int mt = w & 1, nt = w >> 1;
        const int r0 = mt * 16, n0 = nt * 8;
        float acc[4] = {0.f, 0.f, 0.f, 0.f};
        #pragma unroll
        for (int kk = 0; kk < 4; kk++) {
            const int i0 = kk*8;
            unsigned a[4];
            a[0] = __float_as_uint(sm[QR + (r0+gid  )*36 + i0 + tig]);
            a[1] = __float_as_uint(sm[QR + (r0+gid+8)*36 + i0 + tig]);
            a[2] = __float_as_uint(sm[QR + (r0+gid  )*36 + i0 + tig + 4]);
            a[3] = __float_as_uint(sm[QR + (r0+gid+8)*36 + i0 + tig + 4]);
            unsigned b0 = __float_as_uint(sm[W1 + 5120 + (i0+tig  )*136 + n0 + gid]);
            unsigned b1 = __float_as_uint(sm[W1 + 5120 + (i0+tig+4)*136 + n0 + gid]);
            mma8(acc, a, b0, b1);
        }
        const int b0a = QK + (r0+gid)*132 + n0 + 2*tig;
        const int b1a = b0a + 8*132;
        float lo, hi;
        u64 v = *(const u64*)&sm[b0a]; upk(v, lo, hi);
        *(u64*)&sm[b0a] = pk2(lo * sigm(acc[0]), hi * sigm(acc[1]));
        v = *(const u64*)&sm[b1a]; upk(v, lo, hi);
        *(u64*)&sm[b1a] = pk2(lo * sigm(acc[2]), hi * sigm(acc[3]));
    }
    __syncthreads();

    // ============ stage H: residual gate (warp = row; x from L2-hot gmem) ============
    {
        const float bgv = __ldg(bg);
        const int row = w;
        const float* xr = x + (rowBase + row)*128;
        float p = 0.0f;
        #pragma unroll
        for (int k = 0; k < 4; k++) {
            const int cx = lane + 32*k;
            p += sm[W1 + 9472 + cx]       * __ldg(xr + cx);
            p += sm[W1 + 9472 + 128 + cx] * sm[QK + row*132 + cx];
        }
        #pragma unroll
        for (int o = 16; o; o >>= 1) p += __shfl_xor_sync(0xffffffffu, p, o);
        if (lane == 0) sm[GG + row] = sigm(p + bgv);
    }
    __syncthreads();

    // ============ stage I: out = g*o3 + (1-g)*x ============
    {
        const float4* xg = (const float4*)x + rowBase*32;
        float4* og4 = (float4*)out + rowBase*32;
        const int r = t >> 5, c4 = t & 31;
        const float g = sm[GG + r];
        float4 xv = __ldg(&xg[t]);
        float4 ov = *(const float4*)&sm[QK + r*132 + c4*4];
        float4 res;
        res.x = g*ov.x + (1.0f-g)*xv.x;
        res.y = g*ov.y + (1.0f-g)*xv.y;
        res.z = g*ov.z + (1.0f-g)*xv.z;
        res.w = g*ov.w + (1.0f-g)*xv.w;
        og4[t] = res;
    }
}

// =======================================================================
extern "C" void kernel_launch(void* const* d_in, const int* in_sizes, int n_in,
                              void* d_out, int out_size)
{
    const float* x    = (const float*)d_in[0];
    const float* nb   = (const float*)d_in[1];
    const float* Wq   = (const float*)d_in[2];
    const float* bq   = (const float*)d_in[3];
    const float* Wk   = (const float*)d_in[4];
    // d_in[5] = bk : constant over n => softmax-invariant, unused
    const float* Wv   = (const float*)d_in[6];
    const float* bv   = (const float*)d_in[7];
    const float* Wo   = (const float*)d_in[8];
    const float* bo   = (const float*)d_in[9];
    const float* Wse1 = (const float*)d_in[10];
    const float* Wse2 = (const float*)d_in[11];
    const float* Wg   = (const float*)d_in[12];
    const float* bg   = (const float*)d_in[13];
    float* out = (float*)d_out;

    cudaFuncSetAttribute(k_fused, cudaFuncAttributeMaxDynamicSharedMemorySize,
                         SMEM_FLOATS * 4);

    k_pre<<<64, 256>>>(Wq, bq, Wk, Wv, Wo, Wse1, Wse2);
    k_fused<<<2048, 1024, SMEM_FLOATS * 4>>>(x, nb, bv, bo, Wg, bg, out);
}

// round 17
// speedup vs baseline: 1.1770x; 1.1052x over previous
#include <cuda_runtime.h>
#include <math.h>

typedef unsigned long long u64;

// ---------------- pretransposed tf32 weights (device scratch, L2-resident) ----------------
__device__ float g_WqT[16384];   // [c][j]  = tf32(Wq[j][c] * 1/sqrt(32))
__device__ float g_WkN[16384];   // [j][c]  = tf32(Wk[j][c])
__device__ float g_WvT[16384];   // [c][j]  = tf32(Wv[j][c])
__device__ float g_WoP[16384];   // [j][oc] = tf32(Wo[oc][(j&31)*4 + (j>>5)])
__device__ float g_Se1T[4096];   // [oc][i] = tf32(Wse1[i][oc])
__device__ float g_Se2T[4096];   // [i][oc] = tf32(Wse2[oc][i])
__device__ float g_bqs[128];     // bq * 1/sqrt(32)  (fp32 exact)

#define SCALE 0.17677669529663687f

__device__ __forceinline__ unsigned f2tf(float f) {
    unsigned r; asm("cvt.rna.tf32.f32 %0, %1;" : "=r"(r) : "f"(f)); return r;
}
__device__ __forceinline__ float tfbits(float f) {
    return __uint_as_float(f2tf(f));
}

__global__ void k_pre(const float* __restrict__ Wq, const float* __restrict__ bq,
                      const float* __restrict__ Wk,
                      const float* __restrict__ Wv, const float* __restrict__ Wo,
                      const float* __restrict__ Wse1, const float* __restrict__ Wse2)
{
    int i = blockIdx.x * 256 + threadIdx.x;
    if (i < 16384) {
        int a = i >> 7, b = i & 127;
        g_WqT[i] = tfbits(Wq[b*128 + a] * SCALE);
        g_WkN[i] = tfbits(Wk[i]);
        g_WvT[i] = tfbits(Wv[b*128 + a]);
        int j = a, oc = b;
        g_WoP[i] = tfbits(Wo[oc*128 + ((j & 31)*4 + (j >> 5))]);
    }
    if (i < 4096) {
        int oc1 = i >> 5, i1 = i & 31;
        g_Se1T[i] = tfbits(Wse1[i1*128 + oc1]);
        int i2 = i >> 7, oc2 = i & 127;
        g_Se2T[i] = tfbits(Wse2[oc2*32 + i2]);
    }
    if (i < 128) g_bqs[i] = bq[i] * SCALE;
}

// ---------------- helpers ----------------
__device__ __forceinline__ u64 pk2(float lo, float hi) {
    u64 r; asm("mov.b64 %0, {%1, %2};" : "=l"(r) : "f"(lo), "f"(hi)); return r;
}
__device__ __forceinline__ void upk(u64 v, float& lo, float& hi) {
    asm("mov.b64 {%0, %1}, %2;" : "=f"(lo), "=f"(hi) : "l"(v));
}
__device__ __forceinline__ u64 fma2(u64 a, u64 b, u64 c) {
    u64 d; asm("fma.rn.f32x2 %0, %1, %2, %3;" : "=l"(d) : "l"(a), "l"(b), "l"(c)); return d;
}
__device__ __forceinline__ u64 add2(u64 a, u64 b) {
    u64 d; asm("add.rn.f32x2 %0, %1, %2;" : "=l"(d) : "l"(a), "l"(b)); return d;
}
__device__ __forceinline__ void mma8(float d[4], const unsigned a[4],
                                     unsigned b0, unsigned b1) {
    asm volatile(
        "mma.sync.aligned.m16n8k8.row.col.f32.tf32.tf32.f32 "
        "{%0,%1,%2,%3}, {%4,%5,%6,%7}, {%8,%9}, {%0,%1,%2,%3};"
        : "+f"(d[0]), "+f"(d[1]), "+f"(d[2]), "+f"(d[3])
        : "r"(a[0]), "r"(a[1]), "r"(a[2]), "r"(a[3]), "r"(b0), "r"(b1));
}
__device__ __forceinline__ unsigned ldw(const float* p) {   // weight bits from gmem (L2)
    return __float_as_uint(__ldg(p));
}
__device__ __forceinline__ float sigm(float z) { return 1.0f / (1.0f + __expf(-z)); }

// ---------------- smem layout (floats), 32 rows/block, 512 threads, 2 CTAs/SM ----------------
#define QR   0        // 4224:  q[r][132](tf32) -> attn[row][80](fp32) -> o[r][132](tf32) -> T1[r][36](tf32)
#define QK   4224     // 16512: x[r][132](tf32) -> qk[r][516](fp32) -> ctx[r][516](tf32) -> o2[r][132](fp32)
#define GG   (QR + 2560)   // 32 gates (o dead by stage H)
#define SMEM_FLOATS 20736  // 82944 B  -> 2 CTAs/SM

__global__ void __launch_bounds__(512, 2) k_fused(
    const float* __restrict__ x,
    const float* __restrict__ nb,
    const float* __restrict__ bv, const float* __restrict__ bo,
    const float* __restrict__ Wg, const float* __restrict__ bg,
    float* __restrict__ out)
{
    extern __shared__ float sm[];
    const int t = threadIdx.x;
    const int lane = t & 31;
    const int w = t >> 5;               // warp 0..15
    const int gid = lane >> 2;          // mma group id (row-ish)
    const int tig = lane & 3;           // thread-in-group (col-ish)
    const long rowBase = (long)blockIdx.x * 32;

    // ============ phase 0: x -> QK as tf32 bits ============
    {
        const float4* xg = (const float4*)x + rowBase*32;
        #pragma unroll
        for (int it = 0; it < 2; it++) {
            int idx = t + 512*it;
            int r = idx >> 5, c4 = idx & 31;
            float4 v = xg[idx];
            *(float4*)&sm[QK + r*132 + c4*4] =
                make_float4(tfbits(v.x), tfbits(v.y), tfbits(v.z), tfbits(v.w));
        }
    }
    __syncthreads();

    // ============ stage A (mma): q = s*(Wq x + bq) -> QR tf32 ============
    {
        const int mt = w & 1, ng = w >> 1;      // ng 0..7
        const int r0 = mt * 16;
        float acc[2][4];
        #pragma unroll
        for (int nt = 0; nt < 2; nt++)
            #pragma unroll
            for (int p = 0; p < 4; p++) acc[nt][p] = 0.0f;
        #pragma unroll 4
        for (int kk = 0; kk < 16; kk++) {
            const int c0 = kk*8;
            unsigned a[4];
            a[0] = __float_as_uint(sm[QK + (r0+gid  )*132 + c0 + tig]);
            a[1] = __float_as_uint(sm[QK + (r0+gid+8)*132 + c0 + tig]);
            a[2] = __float_as_uint(sm[QK + (r0+gid  )*132 + c0 + tig + 4]);
            a[3] = __float_as_uint(sm[QK + (r0+gid+8)*132 + c0 + tig + 4]);
            #pragma unroll
            for (int nt = 0; nt < 2; nt++) {
                const int n0 = ng*16 + nt*8;
                unsigned b0 = ldw(g_WqT + (c0+tig  )*128 + n0 + gid);
                unsigned b1 = ldw(g_WqT + (c0+tig+4)*128 + n0 + gid);
                mma8(acc[nt], a, b0, b1);
            }
        }
        #pragma unroll
        for (int nt = 0; nt < 2; nt++) {
            const int n0 = ng*16 + nt*8;
            float bj0 = __ldg(&g_bqs[n0 + 2*tig]);
            float bj1 = __ldg(&g_bqs[n0 + 2*tig + 1]);
            const int base = QR + (r0+gid)*132 + n0 + 2*tig;
            *(u64*)&sm[base]         = pk2(tfbits(acc[nt][0]+bj0), tfbits(acc[nt][1]+bj1));
            *(u64*)&sm[base + 8*132] = pk2(tfbits(acc[nt][2]+bj0), tfbits(acc[nt][3]+bj1));
        }
    }
    __syncthreads();   // q visible; x reads complete (B overwrites x region)

    // ============ stage B (mma): qk[r][512] -> QK fp32 (over x) ============
    // Warp covers 64 qk cols (head-local ng*64..+63), split in 2 halves of 32.
    {
        const int h = w & 3, mt = (w>>2)&1, ng = w >> 3;   // ng 0..1
        const int r0 = mt * 16;
        #pragma unroll
        for (int half = 0; half < 2; half++) {
            float acc[4][4];
            #pragma unroll
            for (int i = 0; i < 4; i++)
                #pragma unroll
                for (int p = 0; p < 4; p++) acc[i][p] = 0.0f;
            #pragma unroll
            for (int kk = 0; kk < 4; kk++) {
                const int jc = h*32 + kk*8;
                unsigned a[4];
                a[0] = __float_as_uint(sm[QR + (r0+gid  )*132 + jc + tig]);
                a[1] = __float_as_uint(sm[QR + (r0+gid+8)*132 + jc + tig]);
                a[2] = __float_as_uint(sm[QR + (r0+gid  )*132 + jc + tig + 4]);
                a[3] = __float_as_uint(sm[QR + (r0+gid+8)*132 + jc + tig + 4]);
                #pragma unroll
                for (int i = 0; i < 4; i++) {
                    const int cl = ng*64 + half*32 + i*8;   // head-local Wk col
                    unsigned b0 = ldw(g_WkN + (jc+tig  )*128 + cl + gid);
                    unsigned b1 = ldw(g_WkN + (jc+tig+4)*128 + cl + gid);
                    mma8(acc[i], a, b0, b1);
                }
            }
            #pragma unroll
            for (int i = 0; i < 4; i++) {
                const int gq = h*128 + ng*64 + half*32 + i*8;   // global qk col
                const int base = QK + (r0+gid)*516 + gq + 2*tig;
                *(u64*)&sm[base]         = pk2(acc[i][0], acc[i][1]);
                *(u64*)&sm[base + 8*516] = pk2(acc[i][2], acc[i][3]);
            }
        }
    }
    __syncthreads();   // qk visible to C1

    // ============ stage C1+C2: scores + softmax (warp = row, 2 passes, exact fp32) ============
    #pragma unroll
    for (int pass = 0; pass < 2; pass++) {
        const int row = w + pass*16;
        const int n = (lane < 20) ? lane : 19;
        const float* nbr = nb + (((rowBase + row)*20 + n) << 7);
        const float* qkr = sm + QK + row*516;
        u64 acc[4][2];
        #pragma unroll
        for (int h = 0; h < 4; h++) { acc[h][0] = 0ull; acc[h][1] = 0ull; }
        #pragma unroll 4
        for (int c4 = 0; c4 < 32; c4++) {
            float4 v = *(const float4*)(nbr + c4*4);
            u64 v01 = pk2(v.x, v.y), v23 = pk2(v.z, v.w);
            #pragma unroll
            for (int h = 0; h < 4; h++) {
                float4 qv = *(const float4*)(qkr + h*128 + c4*4);
                acc[h][0] = fma2(pk2(qv.x, qv.y), v01, acc[h][0]);
                acc[h][1] = fma2(pk2(qv.z, qv.w), v23, acc[h][1]);
            }
        }
        float sc[4];
        #pragma unroll
        for (int h = 0; h < 4; h++) {
            u64 s2 = add2(acc[h][0], acc[h][1]);
            float lo, hi; upk(s2, lo, hi);
            sc[h] = (lane < 20) ? (lo + hi) : -1e30f;
        }
        float m[4];
        #pragma unroll
        for (int h = 0; h < 4; h++) m[h] = sc[h];
        #pragma unroll
        for (int o = 16; o; o >>= 1) {
            #pragma unroll
            for (int h = 0; h < 4; h++)
                m[h] = fmaxf(m[h], __shfl_xor_sync(0xffffffffu, m[h], o));
        }
        float e[4], s[4];
        #pragma unroll
        for (int h = 0; h < 4; h++) { e[h] = __expf(sc[h] - m[h]); s[h] = e[h]; }
        #pragma unroll
        for (int o = 16; o; o >>= 1) {
            #pragma unroll
            for (int h = 0; h < 4; h++)
                s[h] += __shfl_xor_sync(0xffffffffu, s[h], o);
        }
        if (lane < 20)
            *(float4*)&sm[QR + row*80 + lane*4] =
                make_float4(e[0]/s[0], e[1]/s[1], e[2]/s[2], e[3]/s[3]);
    }
    __syncwarp();      // attn visible within warp (rows warp-private)

    // ============ stage C3: ctx -> QK as tf32 bits (warp = row, 2 passes) ============
    #pragma unroll
    for (int pass = 0; pass < 2; pass++) {
        const int row = w + pass*16;
        const float* nbr = nb + ((rowBase + row)*20 << 7);
        u64 acc[4][2];
        #pragma unroll
        for (int ch = 0; ch < 4; ch++) { acc[ch][0] = 0ull; acc[ch][1] = 0ull; }
        #pragma unroll 4
        for (int n = 0; n < 20; n++) {
            float4 at = *(const float4*)&sm[QR + row*80 + n*4];   // broadcast
            u64 a01 = pk2(at.x, at.y), a23 = pk2(at.z, at.w);
            #pragma unroll
            for (int ch = 0; ch < 4; ch++) {
                float v = __ldg(nbr + n*128 + ch*32 + lane);
                u64 vp = pk2(v, v);
                acc[ch][0] = fma2(a01, vp, acc[ch][0]);
                acc[ch][1] = fma2(a23, vp, acc[ch][1]);
            }
        }
        #pragma unroll
        for (int ch = 0; ch < 4; ch++) {
            const int c = ch*32 + lane;
            float v0, v1, v2, v3;
            upk(acc[ch][0], v0, v1);
            upk(acc[ch][1], v2, v3);
            sm[QK + row*516 +   0 + c] = tfbits(v0);
            sm[QK + row*516 + 128 + c] = tfbits(v1);
            sm[QK + row*516 + 256 + c] = tfbits(v2);
            sm[QK + row*516 + 384 + c] = tfbits(v3);
        }
    }
    __syncthreads();   // ctx visible to D

    // ============ stage D (mma): o = Wv ctx + bv -> QR tf32 ============
    {
        const int h = w & 3, mt = (w>>2)&1, ng = w >> 3;   // ng 0..1
        const int r0 = mt * 16;
        float acc[2][4];
        #pragma unroll
        for (int nt = 0; nt < 2; nt++)
            #pragma unroll
            for (int p = 0; p < 4; p++) acc[nt][p] = 0.0f;
        #pragma unroll 4
        for (int kk = 0; kk < 16; kk++) {
            const int c0 = kk*8;
            unsigned a[4];
            a[0] = __float_as_uint(sm[QK + (r0+gid  )*516 + h*128 + c0 + tig]);
            a[1] = __float_as_uint(sm[QK + (r0+gid+8)*516 + h*128 + c0 + tig]);
            a[2] = __float_as_uint(sm[QK + (r0+gid  )*516 + h*128 + c0 + tig + 4]);
            a[3] = __float_as_uint(sm[QK + (r0+gid+8)*516 + h*128 + c0 + tig + 4]);
            #pragma unroll
            for (int nt = 0; nt < 2; nt++) {
                const int jg = h*32 + ng*16 + nt*8;     // global j
                unsigned b0 = ldw(g_WvT + (c0+tig  )*128 + jg + gid);
                unsigned b1 = ldw(g_WvT + (c0+tig+4)*128 + jg + gid);
                mma8(acc[nt], a, b0, b1);
            }
        }
        #pragma unroll
        for (int nt = 0; nt < 2; nt++) {
            const int jg = h*32 + ng*16 + nt*8 + 2*tig;
            float bj0 = __ldg(&bv[jg]), bj1 = __ldg(&bv[jg+1]);
            const int base = QR + (r0+gid)*132 + jg - 2*tig + 2*tig;   // = QR + (r0+gid)*132 + jg
            *(u64*)&sm[base]         = pk2(tfbits(acc[nt][0]+bj0), tfbits(acc[nt][1]+bj1));
            *(u64*)&sm[base + 8*132] = pk2(tfbits(acc[nt][2]+bj0), tfbits(acc[nt][3]+bj1));
        }
    }
    __syncthreads();   // o visible; ctx reads complete (E overwrites ctx region)

    // ============ stage E (mma): o2 = WoP o + bo -> QK fp32 (over ctx) ============
    {
        const int mt = w & 1, ng = w >> 1;      // ng 0..7
        const int r0 = mt * 16;
        float acc[2][4];
        #pragma unroll
        for (int nt = 0; nt < 2; nt++)
            #pragma unroll
            for (int p = 0; p < 4; p++) acc[nt][p] = 0.0f;
        #pragma unroll 4
        for (int kk = 0; kk < 16; kk++) {
            const int j0 = kk*8;
            unsigned a[4];
            a[0] = __float_as_uint(sm[QR + (r0+gid  )*132 + j0 + tig]);
            a[1] = __float_as_uint(sm[QR + (r0+gid+8)*132 + j0 + tig]);
            a[2] = __float_as_uint(sm[QR + (r0+gid  )*132 + j0 + tig + 4]);
            a[3] = __float_as_uint(sm[QR + (r0+gid+8)*132 + j0 + tig + 4]);
            #pragma unroll
            for (int nt = 0; nt < 2; nt++) {
                const int n0 = ng*16 + nt*8;
                unsigned b0 = ldw(g_WoP + (j0+tig  )*128 + n0 + gid);
                unsigned b1 = ldw(g_WoP + (j0+tig+4)*128 + n0 + gid);
                mma8(acc[nt], a, b0, b1);
            }
        }
        #pragma unroll
        for (int nt = 0; nt < 2; nt++) {
            const int n0 = ng*16 + nt*8;
            float bj0 = __ldg(&bo[n0 + 2*tig]);
            float bj1 = __ldg(&bo[n0 + 2*tig + 1]);
            const int base = QK + (r0+gid)*132 + n0 + 2*tig;
            *(u64*)&sm[base]         = pk2(acc[nt][0]+bj0, acc[nt][1]+bj1);
            *(u64*)&sm[base + 8*132] = pk2(acc[nt][2]+bj0, acc[nt][3]+bj1);
        }
    }
    __syncthreads();   // o2 visible to F

    // ============ stage F (mma, 8 warps): T1 = relu(Se1 . o2) -> QR tf32 ============
    if (w < 8) {
        const int mt = w & 1, nt = w >> 1;      // nt 0..3
        const int r0 = mt * 16, n0 = nt * 8;
        float acc[4] = {0.f, 0.f, 0.f, 0.f};
        #pragma unroll 4
        for (int kk = 0; kk < 16; kk++) {
            const int k0 = kk*8;
            unsigned a[4];
            a[0] = f2tf(sm[QK + (r0+gid  )*132 + k0 + tig]);
            a[1] = f2tf(sm[QK + (r0+gid+8)*132 + k0 + tig]);
            a[2] = f2tf(sm[QK + (r0+gid  )*132 + k0 + tig + 4]);
            a[3] = f2tf(sm[QK + (r0+gid+8)*132 + k0 + tig + 4]);
            unsigned b0 = ldw(g_Se1T + (k0+tig  )*32 + n0 + gid);
            unsigned b1 = ldw(g_Se1T + (k0+tig+4)*32 + n0 + gid);
            mma8(acc, a, b0, b1);
        }
        const int base = QR + (r0+gid)*36 + n0 + 2*tig;
        *(u64*)&sm[base] =
            pk2(tfbits(fmaxf(acc[0],0.f)), tfbits(fmaxf(acc[1],0.f)));
        *(u64*)&sm[base + 8*36] =
            pk2(tfbits(fmaxf(acc[2],0.f)), tfbits(fmaxf(acc[3],0.f)));
    }
    __syncthreads();

    // ============ stage G (mma): o2 *= sigmoid(Se2 . T1) in place ============
    {
        const int mt = w & 1, ng = w >> 1;      // ng 0..7
        const int r0 = mt * 16;
        float acc[2][4];
        #pragma unroll
        for (int nt = 0; nt < 2; nt++)
            #pragma unroll
            for (int p = 0; p < 4; p++) acc[nt][p] = 0.0f;
        #pragma unroll
        for (int kk = 0; kk < 4; kk++) {
            const int i0 = kk*8;
            unsigned a[4];
            a[0] = __float_as_uint(sm[QR + (r0+gid  )*36 + i0 + tig]);
            a[1] = __float_as_uint(sm[QR + (r0+gid+8)*36 + i0 + tig]);
            a[2] = __float_as_uint(sm[QR + (r0+gid  )*36 + i0 + tig + 4]);
            a[3] = __float_as_uint(sm[QR + (r0+gid+8)*36 + i0 + tig + 4]);
            #pragma unroll
            for (int nt = 0; nt < 2; nt++) {
                const int n0 = ng*16 + nt*8;
                unsigned b0 = ldw(g_Se2T + (i0+tig  )*128 + n0 + gid);
                unsigned b1 = ldw(g_Se2T + (i0+tig+4)*128 + n0 + gid);
                mma8(acc[nt], a, b0, b1);
            }
        }
        #pragma unroll
        for (int nt = 0; nt < 2; nt++) {
            const int n0 = ng*16 + nt*8;
            const int b0a = QK + (r0+gid)*132 + n0 + 2*tig;
            const int b1a = b0a + 8*132;
            float lo, hi;
            u64 v = *(const u64*)&sm[b0a]; upk(v, lo, hi);
            *(u64*)&sm[b0a] = pk2(lo * sigm(acc[nt][0]), hi * sigm(acc[nt][1]));
            v = *(const u64*)&sm[b1a]; upk(v, lo, hi);
            *(u64*)&sm[b1a] = pk2(lo * sigm(acc[nt][2]), hi * sigm(acc[nt][3]));
        }
    }
    __syncthreads();

    // ============ stage H: residual gate (warp = 2 rows; x/Wg from L2 gmem) ============
    {
        const float bgv = __ldg(bg);
        #pragma unroll
        for (int r2 = 0; r2 < 2; r2++) {
            const int row = 2*w + r2;
            const float* xr = x + (rowBase + row)*128;
            float p = 0.0f;
            #pragma unroll
            for (int k = 0; k < 4; k++) {
                const int cx = lane + 32*k;
                p += __ldg(&Wg[cx])       * __ldg(xr + cx);
                p += __ldg(&Wg[128 + cx]) * sm[QK + row*132 + cx];
            }
            #pragma unroll
            for (int o = 16; o; o >>= 1) p += __shfl_xor_sync(0xffffffffu, p, o);
            if (lane == 0) sm[GG + row] = sigm(p + bgv);
        }
    }
    __syncthreads();

    // ============ stage I: out = g*o3 + (1-g)*x ============
    {
        const float4* xg = (const float4*)x + rowBase*32;
        float4* og4 = (float4*)out + rowBase*32;
        #pragma unroll
        for (int it = 0; it < 2; it++) {
            const int idx = t + 512*it;
            const int r = idx >> 5, c4 = idx & 31;
            const float g = sm[GG + r];
            float4 xv = __ldg(&xg[idx]);
            float4 ov = *(const float4*)&sm[QK + r*132 + c4*4];
            float4 res;
            res.x = g*ov.x + (1.0f-g)*xv.x;
            res.y = g*ov.y + (1.0f-g)*xv.y;
            res.z = g*ov.z + (1.0f-g)*xv.z;
            res.w = g*ov.w + (1.0f-g)*xv.w;
            og4[idx] = res;
        }
    }
}

// =======================================================================
extern "C" void kernel_launch(void* const* d_in, const int* in_sizes, int n_in,
                              void* d_out, int out_size)
{
    const float* x    = (const float*)d_in[0];
    const float* nb   = (const float*)d_in[1];
    const float* Wq   = (const float*)d_in[2];
    const float* bq   = (const float*)d_in[3];
    const float* Wk   = (const float*)d_in[4];
    // d_in[5] = bk : constant over n => softmax-invariant, unused
    const float* Wv   = (const float*)d_in[6];
    const float* bv   = (const float*)d_in[7];
    const float* Wo   = (const float*)d_in[8];
    const float* bo   = (const float*)d_in[9];
    const float* Wse1 = (const float*)d_in[10];
    const float* Wse2 = (const float*)d_in[11];
    const float* Wg   = (const float*)d_in[12];
    const float* bg   = (const float*)d_in[13];
    float* out = (float*)d_out;

    cudaFuncSetAttribute(k_fused, cudaFuncAttributeMaxDynamicSharedMemorySize,
                         SMEM_FLOATS * 4);

    k_pre<<<64, 256>>>(Wq, bq, Wk, Wv, Wo, Wse1, Wse2);
    k_fused<<<2048, 512, SMEM_FLOATS * 4>>>(x, nb, bv, bo, Wg, bg, out);
}